// round 1
// baseline (speedup 1.0000x reference)
#include <cuda_runtime.h>
#include <math.h>

#define VOCABN 128
#define HID    1024
#define BATCHN 256
#define SEQ    256

#define BM 32
#define BN 64
#define BKK 32
// 128 threads: tr = tid>>4 in [0,8), tc = tid&15 in [0,16); each thread owns 4x4 outputs.

// Scratch (device globals are the sanctioned scratch path; no allocations).
__device__ float g_P[VOCABN * HID];                       // 512 KB: P[v][k] = embed@Wxh^T + bxh
__device__ float g_hbuf[(size_t)SEQ * BATCHN * HID];      // 256 MB: h_t for all t, layout [t][b][h]

// Generic K-major GEMM: C[m][n] = act( sum_k A[m][k]*Bm[n][k] + bias[n] (+gather) )
// MODE 0: plain (P precompute)          C row-major [M,N]
// MODE 1: step: tanh(acc + bias + P[x[m*SEQ+t]][n]) -> C[m][n], N==HID
// MODE 2: fc:   rows m = s*BATCHN + b, write C[(b*SEQ+s)*N + n], N==VOCABN
template<int MODE>
__global__ __launch_bounds__(128)
void k_gemm(int M, int N, int K,
            const float* __restrict__ A,
            const float* __restrict__ Bm,
            const float* __restrict__ bias,
            float* __restrict__ C,
            const int* __restrict__ x, int t,
            const float* __restrict__ P)
{
    __shared__ float As[2][BM][BKK + 1];
    __shared__ float Bs[2][BN][BKK + 1];

    const int tid = threadIdx.x;
    const int tr  = tid >> 4;
    const int tc  = tid & 15;
    const int m0  = blockIdx.y * BM;
    const int n0  = blockIdx.x * BN;

    float acc[4][4];
#pragma unroll
    for (int i = 0; i < 4; i++)
#pragma unroll
        for (int j = 0; j < 4; j++) acc[i][j] = 0.f;

    const int NT = K / BKK;

    // ---- load tile 0 (vectorized, fully coalesced) ----
#pragma unroll
    for (int i = 0; i < 2; i++) {
        int id = tid + i * 128;
        int mi = id >> 3, k4 = (id & 7) << 2;
        float4 v = *(const float4*)(A + (size_t)(m0 + mi) * K + k4);
        As[0][mi][k4 + 0] = v.x; As[0][mi][k4 + 1] = v.y;
        As[0][mi][k4 + 2] = v.z; As[0][mi][k4 + 3] = v.w;
    }
#pragma unroll
    for (int i = 0; i < 4; i++) {
        int id = tid + i * 128;
        int ni = id >> 3, k4 = (id & 7) << 2;
        float4 v = *(const float4*)(Bm + (size_t)(n0 + ni) * K + k4);
        Bs[0][ni][k4 + 0] = v.x; Bs[0][ni][k4 + 1] = v.y;
        Bs[0][ni][k4 + 2] = v.z; Bs[0][ni][k4 + 3] = v.w;
    }
    __syncthreads();

    int buf = 0;
    for (int kt = 0; kt < NT; kt++) {
        float4 aP[2], bP[4];
        if (kt + 1 < NT) {                       // prefetch next tile into registers
            int k0 = (kt + 1) * BKK;
#pragma unroll
            for (int i = 0; i < 2; i++) {
                int id = tid + i * 128;
                int mi = id >> 3, k4 = (id & 7) << 2;
                aP[i] = *(const float4*)(A + (size_t)(m0 + mi) * K + k0 + k4);
            }
#pragma unroll
            for (int i = 0; i < 4; i++) {
                int id = tid + i * 128;
                int ni = id >> 3, k4 = (id & 7) << 2;
                bP[i] = *(const float4*)(Bm + (size_t)(n0 + ni) * K + k0 + k4);
            }
        }
        // ---- compute current tile (FFMA-bound: 16 FMA + 8 LDS per k) ----
#pragma unroll
        for (int k = 0; k < BKK; k++) {
            float af[4], bf[4];
#pragma unroll
            for (int i = 0; i < 4; i++) af[i] = As[buf][tr * 4 + i][k];
#pragma unroll
            for (int j = 0; j < 4; j++) bf[j] = Bs[buf][tc * 4 + j][k];
#pragma unroll
            for (int i = 0; i < 4; i++)
#pragma unroll
                for (int j = 0; j < 4; j++)
                    acc[i][j] = fmaf(af[i], bf[j], acc[i][j]);
        }
        // ---- stage prefetched tile into the other buffer ----
        if (kt + 1 < NT) {
#pragma unroll
            for (int i = 0; i < 2; i++) {
                int id = tid + i * 128;
                int mi = id >> 3, k4 = (id & 7) << 2;
                As[buf ^ 1][mi][k4 + 0] = aP[i].x; As[buf ^ 1][mi][k4 + 1] = aP[i].y;
                As[buf ^ 1][mi][k4 + 2] = aP[i].z; As[buf ^ 1][mi][k4 + 3] = aP[i].w;
            }
#pragma unroll
            for (int i = 0; i < 4; i++) {
                int id = tid + i * 128;
                int ni = id >> 3, k4 = (id & 7) << 2;
                Bs[buf ^ 1][ni][k4 + 0] = bP[i].x; Bs[buf ^ 1][ni][k4 + 1] = bP[i].y;
                Bs[buf ^ 1][ni][k4 + 2] = bP[i].z; Bs[buf ^ 1][ni][k4 + 3] = bP[i].w;
            }
        }
        __syncthreads();
        buf ^= 1;
    }

    // ---- epilogue ----
#pragma unroll
    for (int i = 0; i < 4; i++) {
        int m = m0 + tr * 4 + i;
        int xr = 0;
        if (MODE == 1) xr = x[m * SEQ + t];
#pragma unroll
        for (int j = 0; j < 4; j++) {
            int n = n0 + tc * 4 + j;
            float v = acc[i][j] + bias[n];
            if (MODE == 1) {
                v = tanhf(v + P[(size_t)xr * HID + n]);
                C[(size_t)m * N + n] = v;
            } else if (MODE == 2) {
                int b = m & (BATCHN - 1);
                int s = m >> 8;                       // BATCHN == 256
                C[((size_t)b * SEQ + s) * N + n] = v;
            } else {
                C[(size_t)m * N + n] = v;
            }
        }
    }
}

// t = 0 step: h0 = 0, so h_1 = tanh(P[x[:,0]] + Whh_b)
__global__ __launch_bounds__(256)
void k_step0(const int* __restrict__ x, const float* __restrict__ P,
             const float* __restrict__ bias, float* __restrict__ hout)
{
    int idx = blockIdx.x * 256 + threadIdx.x;     // B*H threads
    int b = idx >> 10;
    int n = idx & (HID - 1);
    hout[idx] = tanhf(P[(size_t)x[b * SEQ] * HID + n] + bias[n]);
}

__global__ __launch_bounds__(256)
void k_copy4(const float4* __restrict__ src, float4* __restrict__ dst)
{
    int idx = blockIdx.x * 256 + threadIdx.x;
    dst[idx] = src[idx];
}

extern "C" void kernel_launch(void* const* d_in, const int* in_sizes, int n_in,
                              void* d_out, int out_size)
{
    const int*   x     = (const int*)  d_in[0];
    const float* embed = (const float*)d_in[1];
    const float* Wxh_w = (const float*)d_in[2];
    const float* Wxh_b = (const float*)d_in[3];
    const float* Whh_w = (const float*)d_in[4];
    const float* Whh_b = (const float*)d_in[5];
    const float* fc_w  = (const float*)d_in[6];
    const float* fc_b  = (const float*)d_in[7];
    float* outp = (float*)d_out;

    float *P, *hbuf;
    cudaGetSymbolAddress((void**)&P, g_P);
    cudaGetSymbolAddress((void**)&hbuf, g_hbuf);

    // 1) P[v][k] = sum_h embed[v][h]*Wxh[k][h] + bxh[k]   (kills the 137-GFLOP xin GEMM)
    k_gemm<0><<<dim3(HID / BN, VOCABN / BM), 128>>>(
        VOCABN, HID, HID, embed, Wxh_w, Wxh_b, P, nullptr, 0, nullptr);

    // 2) t = 0 (h_prev = 0)
    k_step0<<<(BATCHN * HID) / 256, 256>>>(x, P, Whh_b, hbuf);

    // 3) sequential recurrence: h_t = tanh(P[x[:,t]] + h_{t-1} @ Whh^T + bhh)
    for (int t = 1; t < SEQ; t++) {
        k_gemm<1><<<dim3(HID / BN, BATCHN / BM), 128>>>(
            BATCHN, HID, HID,
            hbuf + (size_t)(t - 1) * BATCHN * HID, Whh_w, Whh_b,
            hbuf + (size_t)t * BATCHN * HID, x, t, P);
    }

    // 4) out[b][s][v] = h_t @ fc^T + fc_b  (rows of A are [s][b][h])
    k_gemm<2><<<dim3(VOCABN / BN, (SEQ * BATCHN) / BM), 128>>>(
        SEQ * BATCHN, VOCABN, HID,
        hbuf, fc_w, fc_b, outp, nullptr, 0, nullptr);

    // 5) hidden = h_{S-1}
    float* hid_dst = outp + (size_t)BATCHN * SEQ * VOCABN;
    k_copy4<<<(BATCHN * HID / 4) / 256, 256>>>(
        (const float4*)(hbuf + (size_t)(SEQ - 1) * BATCHN * HID), (float4*)hid_dst);
}